// round 15
// baseline (speedup 1.0000x reference)
#include <cuda_runtime.h>
#include <cuda_fp16.h>

#define N_NODES 50000
#define N_EDGES 1600000
#define HID 256
#define SCAN_B 196   // ceil(N_NODES/256)

// ---------------- device scratch (static, no allocs) ----------------
__device__ float4   g_agb[N_NODES*HID/4];   // aggr output (tf32 bits) / layer1 aggr (fp32)
__device__ __half   g_h16a[N_NODES*HID];    // h fp16 buffer A
__device__ __half   g_h16b[N_NODES*HID];    // h fp16 buffer B
__device__ unsigned g_W2t[65536];           // W2 in tf32 fragment order
__device__ int      g_deg[N_NODES];
__device__ int      g_rowptr[N_NODES + 1];
__device__ int      g_rank[N_EDGES];        // edge's rank within its dst bucket
__device__ int      g_csrs[N_EDGES];        // src node, grouped by dst
__device__ uint4    g_eah[N_EDGES];         // edge attrs: 8 packed halfs, CSR order
__device__ unsigned long long g_scanst[SCAN_B];  // decoupled-lookback state
__device__ int      g_dhist[256];           // degree histogram (clamped)
__device__ int      g_doff[256];            // bin cursors
__device__ int      g_order[N_NODES];       // nodes sorted by degree
__device__ int      g_flag;                 // 1 = edge_index int64, 0 = int32

__device__ __forceinline__ void red_add_v2(float* a, float x, float y) {
    asm volatile("red.global.add.v2.f32 [%0], {%1,%2};"
                 :: "l"(a), "f"(x), "f"(y) : "memory");
}
__device__ __forceinline__ unsigned to_tf32(float v) {
    unsigned r;
    asm("cvt.rna.tf32.f32 %0, %1;" : "=r"(r) : "f"(v));
    return r;
}
__device__ __forceinline__ int edge_src(const void* ei, int i) {
    return g_flag ? (int)((const long long*)ei)[i] : ((const int*)ei)[i];
}
__device__ __forceinline__ int edge_dst(const void* ei, int i) {
    return g_flag ? (int)((const long long*)ei)[N_EDGES + i]
                  : ((const int*)ei)[N_EDGES + i];
}

// ------- fused prep: detect dtype, W2->tf32 frags, zero scratch -------
__global__ void k_prep(const void* ei, const float* __restrict__ W) {
    int idx = blockIdx.x * 256 + threadIdx.x;   // 65536 threads
    if (idx == 0) {
        const long long* p = (const long long*)ei;
        int is64 = 1;
        for (int i = 0; i < 64; i++) {
            long long v = p[i];
            if (v < 0 || v >= N_NODES) { is64 = 0; break; }
        }
        g_flag = is64;
    }
    {   // W2 fragment table
        int slot = idx & 1;
        int l    = (idx >> 1) & 31;
        int ks   = (idx >> 6) & 31;
        int ct   = idx >> 11;
        int k = ks * 8 + (l & 3) + slot * 4;
        int n = ct * 8 + (l >> 2);
        g_W2t[idx] = to_tf32(W[k * HID + n]);
    }
    if (idx < N_NODES) g_deg[idx] = 0;
    if (idx < SCAN_B)  g_scanst[idx] = 0ULL;
    if (idx < 256)     g_dhist[idx] = 0;
    float* ag = (float*)g_agb;
    for (int i = idx; i < 2 * N_NODES; i += 65536) ag[i] = 0.f;
}

// ---------------- CSR build ----------------
// hist records each edge's rank within its dst bucket (atomicAdd return).
__global__ void k_hist(const void* ei) {
    int i = blockIdx.x * blockDim.x + threadIdx.x;
    if (i < N_EDGES) g_rank[i] = atomicAdd(&g_deg[edge_dst(ei, i)], 1);
}

// single-pass scan via decoupled lookback: deg -> rowptr.
// Also builds the clamped-degree histogram for the node sort.
__global__ void k_scan1() {
    __shared__ int sm[256];
    __shared__ int s_prefix;
    int t = threadIdx.x;
    int bid = blockIdx.x;
    int n = bid * 256 + t;
    int v = (n < N_NODES) ? g_deg[n] : 0;
    if (n < N_NODES) atomicAdd(&g_dhist[v < 255 ? v : 255], 1);
    sm[t] = v;
    __syncthreads();
    for (int o = 1; o < 256; o <<= 1) {
        int u = (t >= o) ? sm[t - o] : 0;
        __syncthreads();
        sm[t] += u;
        __syncthreads();
    }
    int total = sm[255];
    if (t == 0) {
        unsigned long long st;
        if (bid == 0) {
            st = (2ULL << 32) | (unsigned)total;
            atomicExch(&g_scanst[0], st);
            s_prefix = 0;
        } else {
            st = (1ULL << 32) | (unsigned)total;
            atomicExch(&g_scanst[bid], st);
            int pref = 0;
            int p = bid - 1;
            while (true) {
                unsigned long long s2;
                do { s2 = atomicAdd(&g_scanst[p], 0ULL); } while ((s2 >> 32) == 0ULL);
                pref += (int)(unsigned)s2;
                if ((s2 >> 32) == 2ULL) break;
                p--;
            }
            atomicExch(&g_scanst[bid], (2ULL << 32) | (unsigned)(total + pref));
            s_prefix = pref;
        }
    }
    __syncthreads();
    int ex = s_prefix + sm[t] - v;   // exclusive prefix
    if (n < N_NODES) g_rowptr[n] = ex;
    if (bid == SCAN_B - 1 && t == 255) g_rowptr[N_NODES] = N_EDGES;
}

// scan the 256 degree bins -> bin cursors
__global__ void k_dscan() {
    __shared__ int sm[256];
    int t = threadIdx.x;
    int v = g_dhist[t];
    sm[t] = v;
    __syncthreads();
    for (int o = 1; o < 256; o <<= 1) {
        int u = (t >= o) ? sm[t - o] : 0;
        __syncthreads();
        sm[t] += u;
        __syncthreads();
    }
    g_doff[t] = sm[t] - v;   // exclusive
}

// scatter node ids into degree-sorted order
__global__ void k_dorder() {
    int n = blockIdx.x * blockDim.x + threadIdx.x;
    if (n >= N_NODES) return;
    int d = g_deg[n];
    int pos = atomicAdd(&g_doff[d < 255 ? d : 255], 1);
    g_order[pos] = n;
}

// ---------------- fused fill + layer1 scatter (no atomics in CSR path) -----
__global__ void k_fillscat(const void* ei, const float* __restrict__ ea,
                           const float* __restrict__ x,
                           const float* __restrict__ We1,
                           const float* __restrict__ be1) {
    int e = blockIdx.x * blockDim.x + threadIdx.x;
    if (e >= N_EDGES) return;
    int s = edge_src(ei, e);
    int d = edge_dst(ei, e);
    int pos = g_rowptr[d] + g_rank[e];
    float a[7];
    const float* ap = ea + (size_t)e * 7;
#pragma unroll
    for (int k = 0; k < 7; k++) a[k] = ap[k];

    g_csrs[pos] = s;
    uint4 v;
    __half2* p = (__half2*)&v;
    p[0] = __floats2half2_rn(a[0], a[1]);
    p[1] = __floats2half2_rn(a[2], a[3]);
    p[2] = __floats2half2_rn(a[4], a[5]);
    p[3] = __floats2half2_rn(a[6], 0.f);
    g_eah[pos] = v;

    float e0 = __ldg(&be1[0]), e1 = __ldg(&be1[1]);
#pragma unroll
    for (int k = 0; k < 7; k++) {
        e0 += a[k] * __ldg(&We1[k * 2 + 0]);
        e1 += a[k] * __ldg(&We1[k * 2 + 1]);
    }
    float m0 = fmaxf(x[2 * s + 0] + e0, 0.f);
    float m1 = fmaxf(x[2 * s + 1] + e1, 0.f);
    red_add_v2(((float*)g_agb) + 2 * d, m0, m1);
}

// ---------------- layer 1 nn -> fp16 ----------------
__global__ void k_layer1nn(const float* __restrict__ x,
                           const float* __restrict__ W1,
                           const float* __restrict__ b1) {
    int n = blockIdx.x;
    int c = threadIdx.x;
    const float* ag = (const float*)g_agb;
    float a0 = x[2 * n + 0] + ag[2 * n + 0];
    float a1 = x[2 * n + 1] + ag[2 * n + 1];
    float v = b1[c] + a0 * W1[c] + a1 * W1[HID + c];
    g_h16a[n * HID + c] = __float2half(fmaxf(v, 0.f));
}

// ---------------- layers 2/3 aggregation (degree-sorted warps) -------------
// One warp per node via g_order (warps in a block get near-equal degree).
// 8-edge batches; src ids software-pipelined one batch ahead.
__device__ __forceinline__ void aggr_edge_acc(
    __half2 macc[4], const __half2 wh[7][4], const __half2 bh[4],
    uint4 ua, uint4 uh)
{
    const __half2* ap = (const __half2*)&ua;   // (a0,a1)(a2,a3)(a4,a5)(a6,_)
    __half2 a0 = __low2half2(ap[0]),  a1 = __high2half2(ap[0]);
    __half2 a2 = __low2half2(ap[1]),  a3 = __high2half2(ap[1]);
    __half2 a4 = __low2half2(ap[2]),  a5 = __high2half2(ap[2]);
    __half2 a6 = __low2half2(ap[3]);
    const __half2* h2 = (const __half2*)&uh;   // 8 fp16 channels
    __half2 zero = __float2half2_rn(0.f);
#pragma unroll
    for (int c = 0; c < 4; c++) {
        __half2 m = bh[c];
        m = __hfma2(a0, wh[0][c], m);
        m = __hfma2(a1, wh[1][c], m);
        m = __hfma2(a2, wh[2][c], m);
        m = __hfma2(a3, wh[3][c], m);
        m = __hfma2(a4, wh[4][c], m);
        m = __hfma2(a5, wh[5][c], m);
        m = __hfma2(a6, wh[6][c], m);
        m = __hadd2(m, h2[c]);
        m = __hmax2(m, zero);
        macc[c] = __hadd2(macc[c], m);
    }
}

__device__ __forceinline__ void flush_macc(float* accf, const __half2 macc[4]) {
#pragma unroll
    for (int c = 0; c < 4; c++) {
        float2 f = __half22float2(macc[c]);
        accf[2 * c + 0] += f.x;
        accf[2 * c + 1] += f.y;
    }
}

__global__ void __launch_bounds__(256, 2)
k_aggr(int useB, const float* __restrict__ We2, const float* __restrict__ be2) {
    const __half* hin = useB ? g_h16b : g_h16a;
    int gw = (blockIdx.x * blockDim.x + threadIdx.x) >> 5;
    if (gw >= N_NODES) return;
    int node = g_order[gw];
    int lane = threadIdx.x & 31;
    int ch = lane * 8;

    __half2 wh[7][4];
#pragma unroll
    for (int k = 0; k < 7; k++) {
        float4 lo = *(const float4*)&We2[k * HID + ch];
        float4 hi = *(const float4*)&We2[k * HID + ch + 4];
        wh[k][0] = __floats2half2_rn(lo.x, lo.y);
        wh[k][1] = __floats2half2_rn(lo.z, lo.w);
        wh[k][2] = __floats2half2_rn(hi.x, hi.y);
        wh[k][3] = __floats2half2_rn(hi.z, hi.w);
    }
    __half2 bh[4];
    {
        float4 lo = *(const float4*)&be2[ch];
        float4 hi = *(const float4*)&be2[ch + 4];
        bh[0] = __floats2half2_rn(lo.x, lo.y);
        bh[1] = __floats2half2_rn(lo.z, lo.w);
        bh[2] = __floats2half2_rn(hi.x, hi.y);
        bh[3] = __floats2half2_rn(hi.z, hi.w);
    }

    float accf[8];
    {
        uint4 uh = *(const uint4*)&hin[node * HID + ch];
        const __half2* h2 = (const __half2*)&uh;
#pragma unroll
        for (int c = 0; c < 4; c++) {
            float2 f = __half22float2(h2[c]);
            accf[2 * c + 0] = f.x;
            accf[2 * c + 1] = f.y;
        }
    }

    int beg = g_rowptr[node], end = g_rowptr[node + 1];
    int j = beg;

    int s[8];
    if (j + 8 <= end) {
#pragma unroll
        for (int i = 0; i < 8; i++) s[i] = g_csrs[j + i];
    }

    for (; j + 8 <= end; j += 8) {
        uint4 h0 = *(const uint4*)&hin[s[0] * HID + ch];
        uint4 h1 = *(const uint4*)&hin[s[1] * HID + ch];
        uint4 h2 = *(const uint4*)&hin[s[2] * HID + ch];
        uint4 h3 = *(const uint4*)&hin[s[3] * HID + ch];
        uint4 h4 = *(const uint4*)&hin[s[4] * HID + ch];
        uint4 h5 = *(const uint4*)&hin[s[5] * HID + ch];
        uint4 h6 = *(const uint4*)&hin[s[6] * HID + ch];
        uint4 h7 = *(const uint4*)&hin[s[7] * HID + ch];

        bool more = (j + 16 <= end);
        int sn[8];
        if (more) {
#pragma unroll
            for (int i = 0; i < 8; i++) sn[i] = g_csrs[j + 8 + i];
        }

        {
            uint4 a0 = g_eah[j + 0], a1 = g_eah[j + 1];
            uint4 a2 = g_eah[j + 2], a3 = g_eah[j + 3];
            __half2 macc[4];
            macc[0] = macc[1] = macc[2] = macc[3] = __float2half2_rn(0.f);
            aggr_edge_acc(macc, wh, bh, a0, h0);
            aggr_edge_acc(macc, wh, bh, a1, h1);
            aggr_edge_acc(macc, wh, bh, a2, h2);
            aggr_edge_acc(macc, wh, bh, a3, h3);
            flush_macc(accf, macc);
        }
        {
            uint4 a4 = g_eah[j + 4], a5 = g_eah[j + 5];
            uint4 a6 = g_eah[j + 6], a7 = g_eah[j + 7];
            __half2 macc[4];
            macc[0] = macc[1] = macc[2] = macc[3] = __float2half2_rn(0.f);
            aggr_edge_acc(macc, wh, bh, a4, h4);
            aggr_edge_acc(macc, wh, bh, a5, h5);
            aggr_edge_acc(macc, wh, bh, a6, h6);
            aggr_edge_acc(macc, wh, bh, a7, h7);
            flush_macc(accf, macc);
        }
        if (more) {
#pragma unroll
            for (int i = 0; i < 8; i++) s[i] = sn[i];
        }
    }

    // tail (<8 edges)
    for (; j < end; j++) {
        int sj = g_csrs[j];
        uint4 a = g_eah[j];
        uint4 h = *(const uint4*)&hin[sj * HID + ch];
        __half2 macc[4];
        macc[0] = macc[1] = macc[2] = macc[3] = __float2half2_rn(0.f);
        aggr_edge_acc(macc, wh, bh, a, h);
        flush_macc(accf, macc);
    }

    unsigned* outp = (unsigned*)g_agb + node * HID + ch;
    *(uint4*)outp =
        make_uint4(to_tf32(accf[0]), to_tf32(accf[1]), to_tf32(accf[2]), to_tf32(accf[3]));
    *(uint4*)(outp + 4) =
        make_uint4(to_tf32(accf[4]), to_tf32(accf[5]), to_tf32(accf[6]), to_tf32(accf[7]));
}

// ---------------- tf32 tensor-core GEMM ----------------
__global__ void __launch_bounds__(256)
k_gemm_tc(int layer, const float* __restrict__ b) {
    const unsigned* A = (const unsigned*)g_agb;   // tf32 bits, row-major
    __half* hout = (layer == 2) ? g_h16b : g_h16a;

    __shared__ unsigned As[8 * 4 * 4 * 32];   // [mt][ks][slot][lane]

    int tid = threadIdx.x;
    int lane = tid & 31;
    int warp = tid >> 5;
    int wr = warp >> 1;
    int wc = warp & 1;
    int rowBase = blockIdx.y * 128;
    int colBase16 = blockIdx.x * 16;

    float acc[2][8][4];
#pragma unroll
    for (int i = 0; i < 2; i++)
#pragma unroll
        for (int j = 0; j < 8; j++)
#pragma unroll
            for (int k = 0; k < 4; k++) acc[i][j][k] = 0.f;

    int a_c0 = tid & 7;
    int a_row0 = tid >> 3;
    int a_ks = a_c0 >> 1;
    int a_slot_hi = (a_c0 & 1) << 1;

    for (int kt = 0; kt < HID; kt += 32) {
#pragma unroll
        for (int i = 0; i < 4; i++) {
            int row = a_row0 + 32 * i;
            int grow = rowBase + row;
            uint4 v = make_uint4(0u, 0u, 0u, 0u);
            if (grow < N_NODES)
                v = *(const uint4*)&A[grow * HID + kt + a_c0 * 4];
            int rr = row & 15, mt = row >> 4;
            int slot = (rr >> 3) | a_slot_hi;
            *(uint4*)&As[(((mt * 4 + a_ks) * 4 + slot) * 32 + (rr & 7) * 4)] = v;
        }
        __syncthreads();

        uint2 bf[8];
#pragma unroll
        for (int ntl = 0; ntl < 8; ntl++) {
            int ct = colBase16 + wc * 8 + ntl;
            bf[ntl] = *(const uint2*)&g_W2t[((ct * 32 + (kt >> 3)) * 32 + lane) * 2];
        }
#pragma unroll
        for (int ks = 0; ks < 4; ks++) {
            uint2 bfn[8];
            if (ks < 3) {
#pragma unroll
                for (int ntl = 0; ntl < 8; ntl++) {
                    int ct = colBase16 + wc * 8 + ntl;
                    bfn[ntl] = *(const uint2*)&g_W2t[((ct * 32 + (kt >> 3) + ks + 1) * 32 + lane) * 2];
                }
            }
            unsigned af[2][4];
#pragma unroll
            for (int mtl = 0; mtl < 2; mtl++) {
                int mt = wr * 2 + mtl;
#pragma unroll
                for (int s = 0; s < 4; s++)
                    af[mtl][s] = As[((mt * 4 + ks) * 4 + s) * 32 + lane];
            }
#pragma unroll
            for (int mtl = 0; mtl < 2; mtl++)
#pragma unroll
                for (int ntl = 0; ntl < 8; ntl++) {
                    asm volatile(
                        "mma.sync.aligned.m16n8k8.row.col.f32.tf32.tf32.f32 "
                        "{%0,%1,%2,%3}, {%4,%5,%6,%7}, {%8,%9}, {%0,%1,%2,%3};"
                        : "+f"(acc[mtl][ntl][0]), "+f"(acc[mtl][ntl][1]),
                          "+f"(acc[mtl][ntl][2]), "+f"(acc[mtl][ntl][3])
                        : "r"(af[mtl][0]), "r"(af[mtl][1]),
                          "r"(af[mtl][2]), "r"(af[mtl][3]),
                          "r"(bf[ntl].x), "r"(bf[ntl].y));
                }
            if (ks < 3) {
#pragma unroll
                for (int ntl = 0; ntl < 8; ntl++) bf[ntl] = bfn[ntl];
            }
        }
        __syncthreads();
    }

    int gid = lane >> 2;
    int tig = lane & 3;
#pragma unroll
    for (int mtl = 0; mtl < 2; mtl++) {
        int row0 = rowBase + (wr * 2 + mtl) * 16 + gid;
#pragma unroll
        for (int ntl = 0; ntl < 8; ntl++) {
            int col = colBase16 * 8 + (wc * 8 + ntl) * 8 + tig * 2;
            float2 bv = *(const float2*)&b[col];
            if (row0 < N_NODES) {
                __half2 o = __floats2half2_rn(fmaxf(acc[mtl][ntl][0] + bv.x, 0.f),
                                              fmaxf(acc[mtl][ntl][1] + bv.y, 0.f));
                *(__half2*)&hout[row0 * HID + col] = o;
            }
            if (row0 + 8 < N_NODES) {
                __half2 o = __floats2half2_rn(fmaxf(acc[mtl][ntl][2] + bv.x, 0.f),
                                              fmaxf(acc[mtl][ntl][3] + bv.y, 0.f));
                *(__half2*)&hout[(row0 + 8) * HID + col] = o;
            }
        }
    }
}

// ---------------- final: sigmoid(h @ Wend + bend) ----------------
__global__ void k_final(const float* __restrict__ Wend,
                        const float* __restrict__ bend,
                        float* __restrict__ out) {
    int lane = threadIdx.x & 31;
    int warp = threadIdx.x >> 5;
    int n = blockIdx.x * 8 + warp;
    if (n >= N_NODES) return;
    float s = 0.f;
#pragma unroll
    for (int c = lane * 8; c < HID; c += 256) {
        uint4 uh = *(const uint4*)&g_h16a[n * HID + c];
        const __half2* h2 = (const __half2*)&uh;
        float4 w0 = *(const float4*)&Wend[c];
        float4 w1 = *(const float4*)&Wend[c + 4];
        float2 f0 = __half22float2(h2[0]);
        float2 f1 = __half22float2(h2[1]);
        float2 f2 = __half22float2(h2[2]);
        float2 f3 = __half22float2(h2[3]);
        s += f0.x * w0.x + f0.y * w0.y + f1.x * w0.z + f1.y * w0.w;
        s += f2.x * w1.x + f2.y * w1.y + f3.x * w1.z + f3.y * w1.w;
    }
#pragma unroll
    for (int o = 16; o; o >>= 1) s += __shfl_xor_sync(0xffffffffu, s, o);
    if (lane == 0) out[n] = 1.f / (1.f + __expf(-(s + bend[0])));
}

// ---------------- host ----------------
extern "C" void kernel_launch(void* const* d_in, const int* in_sizes, int n_in,
                              void* d_out, int out_size) {
    const float* x    = (const float*)d_in[0];
    const void*  ei   = d_in[1];
    const float* ea   = (const float*)d_in[2];
    const float* We1  = (const float*)d_in[3];
    const float* be1  = (const float*)d_in[4];
    const float* W1   = (const float*)d_in[5];
    const float* b1   = (const float*)d_in[6];
    const float* We2  = (const float*)d_in[7];
    const float* be2  = (const float*)d_in[8];
    const float* W2   = (const float*)d_in[9];
    const float* b2   = (const float*)d_in[10];
    const float* Wend = (const float*)d_in[11];
    const float* bend = (const float*)d_in[12];
    float* out = (float*)d_out;

    k_prep<<<256, 256>>>(ei, W2);                                     // 0
    k_hist<<<(N_EDGES + 255) / 256, 256>>>(ei);                       // 1
    k_scan1<<<SCAN_B, 256>>>();                                       // 2
    k_dscan<<<1, 256>>>();                                            // 3
    k_dorder<<<SCAN_B, 256>>>();                                      // 4
    k_fillscat<<<(N_EDGES + 255) / 256, 256>>>(ei, ea, x, We1, be1);  // 5
    k_layer1nn<<<N_NODES, 256>>>(x, W1, b1);                          // 6

    // layer 2
    k_aggr<<<(N_NODES * 32 + 255) / 256, 256>>>(0, We2, be2);
    k_gemm_tc<<<dim3(2, (N_NODES + 127) / 128), 256>>>(2, b2);

    // layer 3
    k_aggr<<<(N_NODES * 32 + 255) / 256, 256>>>(1, We2, be2);
    k_gemm_tc<<<dim3(2, (N_NODES + 127) / 128), 256>>>(3, b2);

    k_final<<<(N_NODES + 7) / 8, 256>>>(Wend, bend, out);
}

// round 16
// speedup vs baseline: 1.0487x; 1.0487x over previous
#include <cuda_runtime.h>
#include <cuda_fp16.h>

#define N_NODES 50000
#define N_EDGES 1600000
#define HID 256
#define SCAN_B 196   // ceil(N_NODES/256)

// ---------------- device scratch (static, no allocs) ----------------
__device__ float    g_ag1[N_NODES * 2];     // layer-1 aggr (fp32)
__device__ __half   g_ag16[N_NODES * HID];  // aggr output for GEMM (fp16)
__device__ __half   g_h16a[N_NODES*HID];    // h fp16 buffer A
__device__ __half   g_h16b[N_NODES*HID];    // h fp16 buffer B
__device__ unsigned g_W2t[65536];           // W2 in tf32 fragment order
__device__ int      g_deg[N_NODES];
__device__ int      g_rowptr[N_NODES + 1];
__device__ int      g_rank[N_EDGES];        // edge's rank within its dst bucket
__device__ int      g_csrs[N_EDGES];        // src node, grouped by dst
__device__ uint4    g_eah[N_EDGES];         // edge attrs: 8 packed halfs, CSR order
__device__ unsigned long long g_scanst[SCAN_B];  // decoupled-lookback state
__device__ int      g_flag;                 // 1 = edge_index int64, 0 = int32

__device__ __forceinline__ void red_add_v2(float* a, float x, float y) {
    asm volatile("red.global.add.v2.f32 [%0], {%1,%2};"
                 :: "l"(a), "f"(x), "f"(y) : "memory");
}
__device__ __forceinline__ unsigned to_tf32(float v) {
    unsigned r;
    asm("cvt.rna.tf32.f32 %0, %1;" : "=r"(r) : "f"(v));
    return r;
}
__device__ __forceinline__ int edge_src(const void* ei, int i) {
    return g_flag ? (int)((const long long*)ei)[i] : ((const int*)ei)[i];
}
__device__ __forceinline__ int edge_dst(const void* ei, int i) {
    return g_flag ? (int)((const long long*)ei)[N_EDGES + i]
                  : ((const int*)ei)[N_EDGES + i];
}

// ------- fused prep: detect dtype, W2->tf32 frags, zero scratch -------
__global__ void k_prep(const void* ei, const float* __restrict__ W) {
    int idx = blockIdx.x * 256 + threadIdx.x;   // 65536 threads
    if (idx == 0) {
        const long long* p = (const long long*)ei;
        int is64 = 1;
        for (int i = 0; i < 64; i++) {
            long long v = p[i];
            if (v < 0 || v >= N_NODES) { is64 = 0; break; }
        }
        g_flag = is64;
    }
    {   // W2 fragment table
        int slot = idx & 1;
        int l    = (idx >> 1) & 31;
        int ks   = (idx >> 6) & 31;
        int ct   = idx >> 11;
        int k = ks * 8 + (l & 3) + slot * 4;
        int n = ct * 8 + (l >> 2);
        g_W2t[idx] = to_tf32(W[k * HID + n]);
    }
    if (idx < N_NODES) g_deg[idx] = 0;
    if (idx < SCAN_B)  g_scanst[idx] = 0ULL;
    for (int i = idx; i < 2 * N_NODES; i += 65536) g_ag1[i] = 0.f;
}

// ---------------- CSR build ----------------
__global__ void k_hist(const void* ei) {
    int i = blockIdx.x * blockDim.x + threadIdx.x;
    if (i < N_EDGES) g_rank[i] = atomicAdd(&g_deg[edge_dst(ei, i)], 1);
}

// single-pass scan via decoupled lookback: deg -> rowptr
__global__ void k_scan1() {
    __shared__ int sm[256];
    __shared__ int s_prefix;
    int t = threadIdx.x;
    int bid = blockIdx.x;
    int n = bid * 256 + t;
    int v = (n < N_NODES) ? g_deg[n] : 0;
    sm[t] = v;
    __syncthreads();
    for (int o = 1; o < 256; o <<= 1) {
        int u = (t >= o) ? sm[t - o] : 0;
        __syncthreads();
        sm[t] += u;
        __syncthreads();
    }
    int total = sm[255];
    if (t == 0) {
        unsigned long long st;
        if (bid == 0) {
            st = (2ULL << 32) | (unsigned)total;
            atomicExch(&g_scanst[0], st);
            s_prefix = 0;
        } else {
            st = (1ULL << 32) | (unsigned)total;
            atomicExch(&g_scanst[bid], st);
            int pref = 0;
            int p = bid - 1;
            while (true) {
                unsigned long long s2;
                do { s2 = atomicAdd(&g_scanst[p], 0ULL); } while ((s2 >> 32) == 0ULL);
                pref += (int)(unsigned)s2;
                if ((s2 >> 32) == 2ULL) break;
                p--;
            }
            atomicExch(&g_scanst[bid], (2ULL << 32) | (unsigned)(total + pref));
            s_prefix = pref;
        }
    }
    __syncthreads();
    int ex = s_prefix + sm[t] - v;   // exclusive prefix
    if (n < N_NODES) g_rowptr[n] = ex;
    if (bid == SCAN_B - 1 && t == 255) g_rowptr[N_NODES] = N_EDGES;
}

// ---------------- fused fill + layer1 scatter (no atomics) ----------------
__global__ void k_fillscat(const void* ei, const float* __restrict__ ea,
                           const float* __restrict__ x,
                           const float* __restrict__ We1,
                           const float* __restrict__ be1) {
    int e = blockIdx.x * blockDim.x + threadIdx.x;
    if (e >= N_EDGES) return;
    int s = edge_src(ei, e);
    int d = edge_dst(ei, e);
    int pos = g_rowptr[d] + g_rank[e];
    float a[7];
    const float* ap = ea + (size_t)e * 7;
#pragma unroll
    for (int k = 0; k < 7; k++) a[k] = ap[k];

    g_csrs[pos] = s;
    uint4 v;
    __half2* p = (__half2*)&v;
    p[0] = __floats2half2_rn(a[0], a[1]);
    p[1] = __floats2half2_rn(a[2], a[3]);
    p[2] = __floats2half2_rn(a[4], a[5]);
    p[3] = __floats2half2_rn(a[6], 0.f);
    g_eah[pos] = v;

    float e0 = __ldg(&be1[0]), e1 = __ldg(&be1[1]);
#pragma unroll
    for (int k = 0; k < 7; k++) {
        e0 += a[k] * __ldg(&We1[k * 2 + 0]);
        e1 += a[k] * __ldg(&We1[k * 2 + 1]);
    }
    float m0 = fmaxf(x[2 * s + 0] + e0, 0.f);
    float m1 = fmaxf(x[2 * s + 1] + e1, 0.f);
    red_add_v2(g_ag1 + 2 * d, m0, m1);
}

// ---------------- layer 1 nn -> fp16 ----------------
__global__ void k_layer1nn(const float* __restrict__ x,
                           const float* __restrict__ W1,
                           const float* __restrict__ b1) {
    int n = blockIdx.x;
    int c = threadIdx.x;
    float a0 = x[2 * n + 0] + g_ag1[2 * n + 0];
    float a1 = x[2 * n + 1] + g_ag1[2 * n + 1];
    float v = b1[c] + a0 * W1[c] + a1 * W1[HID + c];
    g_h16a[n * HID + c] = __float2half(fmaxf(v, 0.f));
}

// ---------------- layers 2/3 aggregation (best-known R11 config) -----------
__device__ __forceinline__ void aggr_edge_acc(
    __half2 macc[4], const __half2 wh[7][4], const __half2 bh[4],
    uint4 ua, uint4 uh)
{
    const __half2* ap = (const __half2*)&ua;   // (a0,a1)(a2,a3)(a4,a5)(a6,_)
    __half2 a0 = __low2half2(ap[0]),  a1 = __high2half2(ap[0]);
    __half2 a2 = __low2half2(ap[1]),  a3 = __high2half2(ap[1]);
    __half2 a4 = __low2half2(ap[2]),  a5 = __high2half2(ap[2]);
    __half2 a6 = __low2half2(ap[3]);
    const __half2* h2 = (const __half2*)&uh;   // 8 fp16 channels
    __half2 zero = __float2half2_rn(0.f);
#pragma unroll
    for (int c = 0; c < 4; c++) {
        __half2 m = bh[c];
        m = __hfma2(a0, wh[0][c], m);
        m = __hfma2(a1, wh[1][c], m);
        m = __hfma2(a2, wh[2][c], m);
        m = __hfma2(a3, wh[3][c], m);
        m = __hfma2(a4, wh[4][c], m);
        m = __hfma2(a5, wh[5][c], m);
        m = __hfma2(a6, wh[6][c], m);
        m = __hadd2(m, h2[c]);
        m = __hmax2(m, zero);
        macc[c] = __hadd2(macc[c], m);
    }
}

__device__ __forceinline__ void flush_macc(float* accf, const __half2 macc[4]) {
#pragma unroll
    for (int c = 0; c < 4; c++) {
        float2 f = __half22float2(macc[c]);
        accf[2 * c + 0] += f.x;
        accf[2 * c + 1] += f.y;
    }
}

__global__ void __launch_bounds__(256, 2)
k_aggr(int useB, const float* __restrict__ We2, const float* __restrict__ be2) {
    const __half* hin = useB ? g_h16b : g_h16a;
    int node = (blockIdx.x * blockDim.x + threadIdx.x) >> 5;
    if (node >= N_NODES) return;
    int lane = threadIdx.x & 31;
    int ch = lane * 8;

    __half2 wh[7][4];
#pragma unroll
    for (int k = 0; k < 7; k++) {
        float4 lo = *(const float4*)&We2[k * HID + ch];
        float4 hi = *(const float4*)&We2[k * HID + ch + 4];
        wh[k][0] = __floats2half2_rn(lo.x, lo.y);
        wh[k][1] = __floats2half2_rn(lo.z, lo.w);
        wh[k][2] = __floats2half2_rn(hi.x, hi.y);
        wh[k][3] = __floats2half2_rn(hi.z, hi.w);
    }
    __half2 bh[4];
    {
        float4 lo = *(const float4*)&be2[ch];
        float4 hi = *(const float4*)&be2[ch + 4];
        bh[0] = __floats2half2_rn(lo.x, lo.y);
        bh[1] = __floats2half2_rn(lo.z, lo.w);
        bh[2] = __floats2half2_rn(hi.x, hi.y);
        bh[3] = __floats2half2_rn(hi.z, hi.w);
    }

    float accf[8];
    {
        uint4 uh = *(const uint4*)&hin[node * HID + ch];
        const __half2* h2 = (const __half2*)&uh;
#pragma unroll
        for (int c = 0; c < 4; c++) {
            float2 f = __half22float2(h2[c]);
            accf[2 * c + 0] = f.x;
            accf[2 * c + 1] = f.y;
        }
    }

    int beg = g_rowptr[node], end = g_rowptr[node + 1];
    int j = beg;

    int s[8];
    if (j + 8 <= end) {
#pragma unroll
        for (int i = 0; i < 8; i++) s[i] = g_csrs[j + i];
    }

    for (; j + 8 <= end; j += 8) {
        uint4 h0 = *(const uint4*)&hin[s[0] * HID + ch];
        uint4 h1 = *(const uint4*)&hin[s[1] * HID + ch];
        uint4 h2 = *(const uint4*)&hin[s[2] * HID + ch];
        uint4 h3 = *(const uint4*)&hin[s[3] * HID + ch];
        uint4 h4 = *(const uint4*)&hin[s[4] * HID + ch];
        uint4 h5 = *(const uint4*)&hin[s[5] * HID + ch];
        uint4 h6 = *(const uint4*)&hin[s[6] * HID + ch];
        uint4 h7 = *(const uint4*)&hin[s[7] * HID + ch];

        bool more = (j + 16 <= end);
        int sn[8];
        if (more) {
#pragma unroll
            for (int i = 0; i < 8; i++) sn[i] = g_csrs[j + 8 + i];
        }

        {
            uint4 a0 = g_eah[j + 0], a1 = g_eah[j + 1];
            uint4 a2 = g_eah[j + 2], a3 = g_eah[j + 3];
            __half2 macc[4];
            macc[0] = macc[1] = macc[2] = macc[3] = __float2half2_rn(0.f);
            aggr_edge_acc(macc, wh, bh, a0, h0);
            aggr_edge_acc(macc, wh, bh, a1, h1);
            aggr_edge_acc(macc, wh, bh, a2, h2);
            aggr_edge_acc(macc, wh, bh, a3, h3);
            flush_macc(accf, macc);
        }
        {
            uint4 a4 = g_eah[j + 4], a5 = g_eah[j + 5];
            uint4 a6 = g_eah[j + 6], a7 = g_eah[j + 7];
            __half2 macc[4];
            macc[0] = macc[1] = macc[2] = macc[3] = __float2half2_rn(0.f);
            aggr_edge_acc(macc, wh, bh, a4, h4);
            aggr_edge_acc(macc, wh, bh, a5, h5);
            aggr_edge_acc(macc, wh, bh, a6, h6);
            aggr_edge_acc(macc, wh, bh, a7, h7);
            flush_macc(accf, macc);
        }
        if (more) {
#pragma unroll
            for (int i = 0; i < 8; i++) s[i] = sn[i];
        }
    }

    for (; j < end; j++) {
        int sj = g_csrs[j];
        uint4 a = g_eah[j];
        uint4 h = *(const uint4*)&hin[sj * HID + ch];
        __half2 macc[4];
        macc[0] = macc[1] = macc[2] = macc[3] = __float2half2_rn(0.f);
        aggr_edge_acc(macc, wh, bh, a, h);
        flush_macc(accf, macc);
    }

    // store fp16 for the GEMM (same mantissa as tf32)
    uint4 o;
    __half2* op = (__half2*)&o;
    op[0] = __floats2half2_rn(accf[0], accf[1]);
    op[1] = __floats2half2_rn(accf[2], accf[3]);
    op[2] = __floats2half2_rn(accf[4], accf[5]);
    op[3] = __floats2half2_rn(accf[6], accf[7]);
    *(uint4*)&g_ag16[node * HID + ch] = o;
}

// ---------------- tf32 tensor-core GEMM (double-buffered A, fp16 input) ----
__global__ void __launch_bounds__(256)
k_gemm_tc(int layer, const float* __restrict__ b) {
    const __half* A = g_ag16;
    __half* hout = (layer == 2) ? g_h16b : g_h16a;

    __shared__ unsigned As[2][8 * 4 * 4 * 32];   // [buf][mt][ks][slot][lane]

    int tid = threadIdx.x;
    int lane = tid & 31;
    int warp = tid >> 5;
    int wr = warp >> 1;
    int wc = warp & 1;
    int rowBase = blockIdx.y * 128;
    int colBase16 = blockIdx.x * 16;

    float acc[2][8][4];
#pragma unroll
    for (int i = 0; i < 2; i++)
#pragma unroll
        for (int j = 0; j < 8; j++)
#pragma unroll
            for (int k = 0; k < 4; k++) acc[i][j][k] = 0.f;

    int a_c0 = tid & 7;
    int a_row0 = tid >> 3;
    int a_ks = a_c0 >> 1;
    int a_slot_hi = (a_c0 & 1) << 1;

    // prologue: load tile 0
    uint2 pv[4];
#pragma unroll
    for (int i = 0; i < 4; i++) {
        int grow = rowBase + a_row0 + 32 * i;
        pv[i] = (grow < N_NODES) ? *(const uint2*)&A[grow * HID + a_c0 * 4]
                                 : make_uint2(0u, 0u);
    }
#pragma unroll
    for (int i = 0; i < 4; i++) {
        int row = a_row0 + 32 * i;
        int rr = row & 15, mt = row >> 4;
        int slot = (rr >> 3) | a_slot_hi;
        float2 flo = __half22float2(*(const __half2*)&pv[i].x);
        float2 fhi = __half22float2(*(const __half2*)&pv[i].y);
        uint4 u = make_uint4(to_tf32(flo.x), to_tf32(flo.y), to_tf32(fhi.x), to_tf32(fhi.y));
        *(uint4*)&As[0][(((mt * 4 + a_ks) * 4 + slot) * 32 + (rr & 7) * 4)] = u;
    }
    __syncthreads();

    for (int t = 0; t < 8; t++) {
        int kt = t * 32;
        uint2 nv[4];
        if (t < 7) {
#pragma unroll
            for (int i = 0; i < 4; i++) {
                int grow = rowBase + a_row0 + 32 * i;
                nv[i] = (grow < N_NODES)
                    ? *(const uint2*)&A[grow * HID + kt + 32 + a_c0 * 4]
                    : make_uint2(0u, 0u);
            }
        }
        const unsigned* buf = As[t & 1];

        uint2 bf[8];
#pragma unroll
        for (int ntl = 0; ntl < 8; ntl++) {
            int ct = colBase16 + wc * 8 + ntl;
            bf[ntl] = *(const uint2*)&g_W2t[((ct * 32 + (kt >> 3)) * 32 + lane) * 2];
        }
#pragma unroll
        for (int ks = 0; ks < 4; ks++) {
            uint2 bfn[8];
            if (ks < 3) {
#pragma unroll
                for (int ntl = 0; ntl < 8; ntl++) {
                    int ct = colBase16 + wc * 8 + ntl;
                    bfn[ntl] = *(const uint2*)&g_W2t[((ct * 32 + (kt >> 3) + ks + 1) * 32 + lane) * 2];
                }
            }
            unsigned af[2][4];
#pragma unroll
            for (int mtl = 0; mtl < 2; mtl++) {
                int mt = wr * 2 + mtl;
#pragma unroll
                for (int s = 0; s < 4; s++)
                    af[mtl][s] = buf[((mt * 4 + ks) * 4 + s) * 32 + lane];
            }
#pragma unroll
            for (int mtl = 0; mtl < 2; mtl++)
#pragma unroll
                for (int ntl = 0; ntl < 8; ntl++) {
                    asm volatile(
                        "mma.sync.aligned.m16n8k8.row.col.f32.tf32.tf32.f32 "
                        "{%0,%1,%2,%3}, {%4,%5,%6,%7}, {%8,%9}, {%0,%1,%2,%3};"
                        : "+f"(acc[mtl][ntl][0]), "+f"(acc[mtl][ntl][1]),
                          "+f"(acc[mtl][ntl][2]), "+f"(acc[mtl][ntl][3])
                        : "r"(af[mtl][0]), "r"(af[mtl][1]),
                          "r"(af[mtl][2]), "r"(af[mtl][3]),
                          "r"(bf[ntl].x), "r"(bf[ntl].y));
                }
            if (ks < 3) {
#pragma unroll
                for (int ntl = 0; ntl < 8; ntl++) bf[ntl] = bfn[ntl];
            }
        }

        if (t < 7) {
#pragma unroll
            for (int i = 0; i < 4; i++) {
                int row = a_row0 + 32 * i;
                int rr = row & 15, mt = row >> 4;
                int slot = (rr >> 3) | a_slot_hi;
                float2 flo = __half22float2(*(const __half2*)&nv[i].x);
                float2 fhi = __half22float2(*(const __half2*)&nv[i].y);
                uint4 u = make_uint4(to_tf32(flo.x), to_tf32(flo.y),
                                     to_tf32(fhi.x), to_tf32(fhi.y));
                *(uint4*)&As[(t + 1) & 1][(((mt * 4 + a_ks) * 4 + slot) * 32 + (rr & 7) * 4)] = u;
            }
            __syncthreads();
        }
    }

    int gid = lane >> 2;
    int tig = lane & 3;
#pragma unroll
    for (int mtl = 0; mtl < 2; mtl++) {
        int row0 = rowBase + (wr * 2 + mtl) * 16 + gid;
#pragma unroll
        for (int ntl = 0; ntl < 8; ntl++) {
            int col = colBase16 * 8 + (wc * 8 + ntl) * 8 + tig * 2;
            float2 bv = *(const float2*)&b[col];
            if (row0 < N_NODES) {
                __half2 o = __floats2half2_rn(fmaxf(acc[mtl][ntl][0] + bv.x, 0.f),
                                              fmaxf(acc[mtl][ntl][1] + bv.y, 0.f));
                *(__half2*)&hout[row0 * HID + col] = o;
            }
            if (row0 + 8 < N_NODES) {
                __half2 o = __floats2half2_rn(fmaxf(acc[mtl][ntl][2] + bv.x, 0.f),
                                              fmaxf(acc[mtl][ntl][3] + bv.y, 0.f));
                *(__half2*)&hout[(row0 + 8) * HID + col] = o;
            }
        }
    }
}

// ---------------- final: sigmoid(h @ Wend + bend) ----------------
__global__ void k_final(const float* __restrict__ Wend,
                        const float* __restrict__ bend,
                        float* __restrict__ out) {
    int lane = threadIdx.x & 31;
    int warp = threadIdx.x >> 5;
    int n = blockIdx.x * 8 + warp;
    if (n >= N_NODES) return;
    float s = 0.f;
#pragma unroll
    for (int c = lane * 8; c < HID; c += 256) {
        uint4 uh = *(const uint4*)&g_h16a[n * HID + c];
        const __half2* h2 = (const __half2*)&uh;
        float4 w0 = *(const float4*)&Wend[c];
        float4 w1 = *(const float4*)&Wend[c + 4];
        float2 f0 = __half22float2(h2[0]);
        float2 f1 = __half22float2(h2[1]);
        float2 f2 = __half22float2(h2[2]);
        float2 f3 = __half22float2(h2[3]);
        s += f0.x * w0.x + f0.y * w0.y + f1.x * w0.z + f1.y * w0.w;
        s += f2.x * w1.x + f2.y * w1.y + f3.x * w1.z + f3.y * w1.w;
    }
#pragma unroll
    for (int o = 16; o; o >>= 1) s += __shfl_xor_sync(0xffffffffu, s, o);
    if (lane == 0) out[n] = 1.f / (1.f + __expf(-(s + bend[0])));
}

// ---------------- host ----------------
extern "C" void kernel_launch(void* const* d_in, const int* in_sizes, int n_in,
                              void* d_out, int out_size) {
    const float* x    = (const float*)d_in[0];
    const void*  ei   = d_in[1];
    const float* ea   = (const float*)d_in[2];
    const float* We1  = (const float*)d_in[3];
    const float* be1  = (const float*)d_in[4];
    const float* W1   = (const float*)d_in[5];
    const float* b1   = (const float*)d_in[6];
    const float* We2  = (const float*)d_in[7];
    const float* be2  = (const float*)d_in[8];
    const float* W2   = (const float*)d_in[9];
    const float* b2   = (const float*)d_in[10];
    const float* Wend = (const float*)d_in[11];
    const float* bend = (const float*)d_in[12];
    float* out = (float*)d_out;

    k_prep<<<256, 256>>>(ei, W2);                                     // 0
    k_hist<<<(N_EDGES + 255) / 256, 256>>>(ei);                       // 1
    k_scan1<<<SCAN_B, 256>>>();                                       // 2
    k_fillscat<<<(N_EDGES + 255) / 256, 256>>>(ei, ea, x, We1, be1);  // 3
    k_layer1nn<<<N_NODES, 256>>>(x, W1, b1);                          // 4

    // layer 2
    k_aggr<<<(N_NODES * 32 + 255) / 256, 256>>>(0, We2, be2);
    k_gemm_tc<<<dim3(2, (N_NODES + 127) / 128), 256>>>(2, b2);

    // layer 3
    k_aggr<<<(N_NODES * 32 + 255) / 256, 256>>>(1, We2, be2);
    k_gemm_tc<<<dim3(2, (N_NODES + 127) / 128), 256>>>(3, b2);

    k_final<<<(N_NODES + 7) / 8, 256>>>(Wend, bend, out);
}

// round 17
// speedup vs baseline: 1.1239x; 1.0717x over previous
#include <cuda_runtime.h>
#include <cuda_fp16.h>

#define N_NODES 50000
#define N_EDGES 1600000
#define HID 256
#define SCAN_B 196   // ceil(N_NODES/256)

// ---------------- device scratch (static, no allocs) ----------------
__device__ float    g_ag1[N_NODES * 2];     // layer-1 aggr (fp32)
__device__ __half   g_ag16[N_NODES * HID];  // aggr output for GEMM (fp16)
__device__ __half   g_h16a[N_NODES*HID];    // h fp16 buffer A
__device__ __half   g_h16b[N_NODES*HID];    // h fp16 buffer B
__device__ __half   g_W2h[65536];           // W2 in fp16 m16n8k16 fragment order
__device__ int      g_deg[N_NODES];
__device__ int      g_rowptr[N_NODES + 1];
__device__ int      g_rank[N_EDGES];        // edge's rank within its dst bucket
__device__ int      g_csrs[N_EDGES];        // src node, grouped by dst
__device__ uint4    g_eah[N_EDGES];         // edge attrs: 8 packed halfs, CSR order
__device__ unsigned long long g_scanst[SCAN_B];  // decoupled-lookback state
__device__ int      g_flag;                 // 1 = edge_index int64, 0 = int32

__device__ __forceinline__ void red_add_v2(float* a, float x, float y) {
    asm volatile("red.global.add.v2.f32 [%0], {%1,%2};"
                 :: "l"(a), "f"(x), "f"(y) : "memory");
}
__device__ __forceinline__ int edge_src(const void* ei, int i) {
    return g_flag ? (int)((const long long*)ei)[i] : ((const int*)ei)[i];
}
__device__ __forceinline__ int edge_dst(const void* ei, int i) {
    return g_flag ? (int)((const long long*)ei)[N_EDGES + i]
                  : ((const int*)ei)[N_EDGES + i];
}

// ------- fused prep: detect dtype, W2->fp16 frags, zero scratch -------
// Fragment order for mma.m16n8k16.row.col (B, col-major):
//   half index = (((ct*16 + ks)*32 + lane)*2 + breg)*2 + w
//   k = ks*16 + (lane&3)*2 + breg*8 + w ; n = ct*8 + (lane>>2)
__global__ void k_prep(const void* ei, const float* __restrict__ W) {
    int idx = blockIdx.x * 256 + threadIdx.x;   // 65536 threads
    if (idx == 0) {
        const long long* p = (const long long*)ei;
        int is64 = 1;
        for (int i = 0; i < 64; i++) {
            long long v = p[i];
            if (v < 0 || v >= N_NODES) { is64 = 0; break; }
        }
        g_flag = is64;
    }
    {
        int w    = idx & 1;
        int breg = (idx >> 1) & 1;
        int l    = (idx >> 2) & 31;
        int ks   = (idx >> 7) & 15;
        int ct   = idx >> 11;
        int k = ks * 16 + (l & 3) * 2 + breg * 8 + w;
        int n = ct * 8 + (l >> 2);
        g_W2h[idx] = __float2half(W[k * HID + n]);
    }
    if (idx < N_NODES) g_deg[idx] = 0;
    if (idx < SCAN_B)  g_scanst[idx] = 0ULL;
    for (int i = idx; i < 2 * N_NODES; i += 65536) g_ag1[i] = 0.f;
}

// ---------------- CSR build ----------------
__global__ void k_hist(const void* ei) {
    int i = blockIdx.x * blockDim.x + threadIdx.x;
    if (i < N_EDGES) g_rank[i] = atomicAdd(&g_deg[edge_dst(ei, i)], 1);
}

// single-pass scan via decoupled lookback: deg -> rowptr
__global__ void k_scan1() {
    __shared__ int sm[256];
    __shared__ int s_prefix;
    int t = threadIdx.x;
    int bid = blockIdx.x;
    int n = bid * 256 + t;
    int v = (n < N_NODES) ? g_deg[n] : 0;
    sm[t] = v;
    __syncthreads();
    for (int o = 1; o < 256; o <<= 1) {
        int u = (t >= o) ? sm[t - o] : 0;
        __syncthreads();
        sm[t] += u;
        __syncthreads();
    }
    int total = sm[255];
    if (t == 0) {
        unsigned long long st;
        if (bid == 0) {
            st = (2ULL << 32) | (unsigned)total;
            atomicExch(&g_scanst[0], st);
            s_prefix = 0;
        } else {
            st = (1ULL << 32) | (unsigned)total;
            atomicExch(&g_scanst[bid], st);
            int pref = 0;
            int p = bid - 1;
            while (true) {
                unsigned long long s2;
                do { s2 = atomicAdd(&g_scanst[p], 0ULL); } while ((s2 >> 32) == 0ULL);
                pref += (int)(unsigned)s2;
                if ((s2 >> 32) == 2ULL) break;
                p--;
            }
            atomicExch(&g_scanst[bid], (2ULL << 32) | (unsigned)(total + pref));
            s_prefix = pref;
        }
    }
    __syncthreads();
    int ex = s_prefix + sm[t] - v;   // exclusive prefix
    if (n < N_NODES) g_rowptr[n] = ex;
    if (bid == SCAN_B - 1 && t == 255) g_rowptr[N_NODES] = N_EDGES;
}

// ---------------- fused fill + layer1 scatter (no atomics) ----------------
__global__ void k_fillscat(const void* ei, const float* __restrict__ ea,
                           const float* __restrict__ x,
                           const float* __restrict__ We1,
                           const float* __restrict__ be1) {
    int e = blockIdx.x * blockDim.x + threadIdx.x;
    if (e >= N_EDGES) return;
    int s = edge_src(ei, e);
    int d = edge_dst(ei, e);
    int pos = g_rowptr[d] + g_rank[e];
    float a[7];
    const float* ap = ea + (size_t)e * 7;
#pragma unroll
    for (int k = 0; k < 7; k++) a[k] = ap[k];

    g_csrs[pos] = s;
    uint4 v;
    __half2* p = (__half2*)&v;
    p[0] = __floats2half2_rn(a[0], a[1]);
    p[1] = __floats2half2_rn(a[2], a[3]);
    p[2] = __floats2half2_rn(a[4], a[5]);
    p[3] = __floats2half2_rn(a[6], 0.f);
    g_eah[pos] = v;

    float e0 = __ldg(&be1[0]), e1 = __ldg(&be1[1]);
#pragma unroll
    for (int k = 0; k < 7; k++) {
        e0 += a[k] * __ldg(&We1[k * 2 + 0]);
        e1 += a[k] * __ldg(&We1[k * 2 + 1]);
    }
    float m0 = fmaxf(x[2 * s + 0] + e0, 0.f);
    float m1 = fmaxf(x[2 * s + 1] + e1, 0.f);
    red_add_v2(g_ag1 + 2 * d, m0, m1);
}

// ---------------- layer 1 nn -> fp16 ----------------
__global__ void k_layer1nn(const float* __restrict__ x,
                           const float* __restrict__ W1,
                           const float* __restrict__ b1) {
    int n = blockIdx.x;
    int c = threadIdx.x;
    float a0 = x[2 * n + 0] + g_ag1[2 * n + 0];
    float a1 = x[2 * n + 1] + g_ag1[2 * n + 1];
    float v = b1[c] + a0 * W1[c] + a1 * W1[HID + c];
    g_h16a[n * HID + c] = __float2half(fmaxf(v, 0.f));
}

// ---------------- layers 2/3 aggregation (best-known config) ---------------
__device__ __forceinline__ void aggr_edge_acc(
    __half2 macc[4], const __half2 wh[7][4], const __half2 bh[4],
    uint4 ua, uint4 uh)
{
    const __half2* ap = (const __half2*)&ua;
    __half2 a0 = __low2half2(ap[0]),  a1 = __high2half2(ap[0]);
    __half2 a2 = __low2half2(ap[1]),  a3 = __high2half2(ap[1]);
    __half2 a4 = __low2half2(ap[2]),  a5 = __high2half2(ap[2]);
    __half2 a6 = __low2half2(ap[3]);
    const __half2* h2 = (const __half2*)&uh;
    __half2 zero = __float2half2_rn(0.f);
#pragma unroll
    for (int c = 0; c < 4; c++) {
        __half2 m = bh[c];
        m = __hfma2(a0, wh[0][c], m);
        m = __hfma2(a1, wh[1][c], m);
        m = __hfma2(a2, wh[2][c], m);
        m = __hfma2(a3, wh[3][c], m);
        m = __hfma2(a4, wh[4][c], m);
        m = __hfma2(a5, wh[5][c], m);
        m = __hfma2(a6, wh[6][c], m);
        m = __hadd2(m, h2[c]);
        m = __hmax2(m, zero);
        macc[c] = __hadd2(macc[c], m);
    }
}

__device__ __forceinline__ void flush_macc(float* accf, const __half2 macc[4]) {
#pragma unroll
    for (int c = 0; c < 4; c++) {
        float2 f = __half22float2(macc[c]);
        accf[2 * c + 0] += f.x;
        accf[2 * c + 1] += f.y;
    }
}

__global__ void __launch_bounds__(256, 2)
k_aggr(int useB, const float* __restrict__ We2, const float* __restrict__ be2) {
    const __half* hin = useB ? g_h16b : g_h16a;
    int node = (blockIdx.x * blockDim.x + threadIdx.x) >> 5;
    if (node >= N_NODES) return;
    int lane = threadIdx.x & 31;
    int ch = lane * 8;

    __half2 wh[7][4];
#pragma unroll
    for (int k = 0; k < 7; k++) {
        float4 lo = *(const float4*)&We2[k * HID + ch];
        float4 hi = *(const float4*)&We2[k * HID + ch + 4];
        wh[k][0] = __floats2half2_rn(lo.x, lo.y);
        wh[k][1] = __floats2half2_rn(lo.z, lo.w);
        wh[k][2] = __floats2half2_rn(hi.x, hi.y);
        wh[k][3] = __floats2half2_rn(hi.z, hi.w);
    }
    __half2 bh[4];
    {
        float4 lo = *(const float4*)&be2[ch];
        float4 hi = *(const float4*)&be2[ch + 4];
        bh[0] = __floats2half2_rn(lo.x, lo.y);
        bh[1] = __floats2half2_rn(lo.z, lo.w);
        bh[2] = __floats2half2_rn(hi.x, hi.y);
        bh[3] = __floats2half2_rn(hi.z, hi.w);
    }

    float accf[8];
    {
        uint4 uh = *(const uint4*)&hin[node * HID + ch];
        const __half2* h2 = (const __half2*)&uh;
#pragma unroll
        for (int c = 0; c < 4; c++) {
            float2 f = __half22float2(h2[c]);
            accf[2 * c + 0] = f.x;
            accf[2 * c + 1] = f.y;
        }
    }

    int beg = g_rowptr[node], end = g_rowptr[node + 1];
    int j = beg;

    int s[8];
    if (j + 8 <= end) {
#pragma unroll
        for (int i = 0; i < 8; i++) s[i] = g_csrs[j + i];
    }

    for (; j + 8 <= end; j += 8) {
        uint4 h0 = *(const uint4*)&hin[s[0] * HID + ch];
        uint4 h1 = *(const uint4*)&hin[s[1] * HID + ch];
        uint4 h2 = *(const uint4*)&hin[s[2] * HID + ch];
        uint4 h3 = *(const uint4*)&hin[s[3] * HID + ch];
        uint4 h4 = *(const uint4*)&hin[s[4] * HID + ch];
        uint4 h5 = *(const uint4*)&hin[s[5] * HID + ch];
        uint4 h6 = *(const uint4*)&hin[s[6] * HID + ch];
        uint4 h7 = *(const uint4*)&hin[s[7] * HID + ch];

        bool more = (j + 16 <= end);
        int sn[8];
        if (more) {
#pragma unroll
            for (int i = 0; i < 8; i++) sn[i] = g_csrs[j + 8 + i];
        }

        {
            uint4 a0 = g_eah[j + 0], a1 = g_eah[j + 1];
            uint4 a2 = g_eah[j + 2], a3 = g_eah[j + 3];
            __half2 macc[4];
            macc[0] = macc[1] = macc[2] = macc[3] = __float2half2_rn(0.f);
            aggr_edge_acc(macc, wh, bh, a0, h0);
            aggr_edge_acc(macc, wh, bh, a1, h1);
            aggr_edge_acc(macc, wh, bh, a2, h2);
            aggr_edge_acc(macc, wh, bh, a3, h3);
            flush_macc(accf, macc);
        }
        {
            uint4 a4 = g_eah[j + 4], a5 = g_eah[j + 5];
            uint4 a6 = g_eah[j + 6], a7 = g_eah[j + 7];
            __half2 macc[4];
            macc[0] = macc[1] = macc[2] = macc[3] = __float2half2_rn(0.f);
            aggr_edge_acc(macc, wh, bh, a4, h4);
            aggr_edge_acc(macc, wh, bh, a5, h5);
            aggr_edge_acc(macc, wh, bh, a6, h6);
            aggr_edge_acc(macc, wh, bh, a7, h7);
            flush_macc(accf, macc);
        }
        if (more) {
#pragma unroll
            for (int i = 0; i < 8; i++) s[i] = sn[i];
        }
    }

    for (; j < end; j++) {
        int sj = g_csrs[j];
        uint4 a = g_eah[j];
        uint4 h = *(const uint4*)&hin[sj * HID + ch];
        __half2 macc[4];
        macc[0] = macc[1] = macc[2] = macc[3] = __float2half2_rn(0.f);
        aggr_edge_acc(macc, wh, bh, a, h);
        flush_macc(accf, macc);
    }

    uint4 o;
    __half2* op = (__half2*)&o;
    op[0] = __floats2half2_rn(accf[0], accf[1]);
    op[1] = __floats2half2_rn(accf[2], accf[3]);
    op[2] = __floats2half2_rn(accf[4], accf[5]);
    op[3] = __floats2half2_rn(accf[6], accf[7]);
    *(uint4*)&g_ag16[node * HID + ch] = o;
}

// ---------------- fp16 m16n8k16 tensor-core GEMM ---------------------------
// Block 128x128, 8 warps, warp tile 32x64. A stays fp16: smem is row-major
// with rows padded to 36 halfs (72B) for conflict-free 4B fragment reads.
// B fragments stream from the fp16 table g_W2h (L2-resident, 128KB).
#define AROW 36
__global__ void __launch_bounds__(256)
k_gemm_tc(int layer, const float* __restrict__ b) {
    const __half* A = g_ag16;
    __half* hout = (layer == 2) ? g_h16b : g_h16a;

    __shared__ __half As[2][128 * AROW];

    int tid = threadIdx.x;
    int lane = tid & 31;
    int warp = tid >> 5;
    int wr = warp >> 1;          // 0..3
    int wc = warp & 1;           // 0..1
    int gid = lane >> 2;
    int tig = lane & 3;
    int rowBase = blockIdx.y * 128;
    int colBase16 = blockIdx.x * 16;   // ct base

    float acc[2][8][4];
#pragma unroll
    for (int i = 0; i < 2; i++)
#pragma unroll
        for (int j = 0; j < 8; j++)
#pragma unroll
            for (int k = 0; k < 4; k++) acc[i][j][k] = 0.f;

    int a_c0 = tid & 7;          // 8B column group (4 halfs)
    int a_row0 = tid >> 3;       // 0..31

    // prologue: load + store tile 0
    uint2 pv[4];
#pragma unroll
    for (int i = 0; i < 4; i++) {
        int grow = rowBase + a_row0 + 32 * i;
        pv[i] = (grow < N_NODES) ? *(const uint2*)&A[grow * HID + a_c0 * 4]
                                 : make_uint2(0u, 0u);
    }
#pragma unroll
    for (int i = 0; i < 4; i++) {
        int row = a_row0 + 32 * i;
        *(uint2*)&As[0][row * AROW + a_c0 * 4] = pv[i];
    }
    __syncthreads();

    for (int t = 0; t < 8; t++) {
        int kt = t * 32;
        uint2 nv[4];
        if (t < 7) {
#pragma unroll
            for (int i = 0; i < 4; i++) {
                int grow = rowBase + a_row0 + 32 * i;
                nv[i] = (grow < N_NODES)
                    ? *(const uint2*)&A[grow * HID + kt + 32 + a_c0 * 4]
                    : make_uint2(0u, 0u);
            }
        }
        const __half* buf = As[t & 1];

#pragma unroll
        for (int ks = 0; ks < 2; ks++) {       // two k=16 steps per 32-k tile
            int kst = (kt >> 4) + ks;          // global k-tile index 0..15
            // B fragments for this ks
            uint2 bf[8];
#pragma unroll
            for (int ntl = 0; ntl < 8; ntl++) {
                int ct = colBase16 + wc * 8 + ntl;
                bf[ntl] = *(const uint2*)&g_W2h[((ct * 16 + kst) * 32 + lane) * 4];
            }
            // A fragments
            unsigned af[2][4];
#pragma unroll
            for (int mtl = 0; mtl < 2; mtl++) {
                int r0 = (wr * 2 + mtl) * 16 + gid;
                const __half* base = &buf[r0 * AROW + ks * 16 + tig * 2];
                af[mtl][0] = *(const unsigned*)(base);
                af[mtl][1] = *(const unsigned*)(base + 8 * AROW);
                af[mtl][2] = *(const unsigned*)(base + 8);
                af[mtl][3] = *(const unsigned*)(base + 8 * AROW + 8);
            }
#pragma unroll
            for (int mtl = 0; mtl < 2; mtl++)
#pragma unroll
                for (int ntl = 0; ntl < 8; ntl++) {
                    asm volatile(
                        "mma.sync.aligned.m16n8k16.row.col.f32.f16.f16.f32 "
                        "{%0,%1,%2,%3}, {%4,%5,%6,%7}, {%8,%9}, {%0,%1,%2,%3};"
                        : "+f"(acc[mtl][ntl][0]), "+f"(acc[mtl][ntl][1]),
                          "+f"(acc[mtl][ntl][2]), "+f"(acc[mtl][ntl][3])
                        : "r"(af[mtl][0]), "r"(af[mtl][1]),
                          "r"(af[mtl][2]), "r"(af[mtl][3]),
                          "r"(bf[ntl].x), "r"(bf[ntl].y));
                }
        }

        if (t < 7) {
#pragma unroll
            for (int i = 0; i < 4; i++) {
                int row = a_row0 + 32 * i;
                *(uint2*)&As[(t + 1) & 1][row * AROW + a_c0 * 4] = nv[i];
            }
            __syncthreads();
        }
    }

    // epilogue: bias + relu -> fp16
#pragma unroll
    for (int mtl = 0; mtl < 2; mtl++) {
        int row0 = rowBase + (wr * 2 + mtl) * 16 + gid;
#pragma unroll
        for (int ntl = 0; ntl < 8; ntl++) {
            int col = colBase16 * 8 + (wc * 8 + ntl) * 8 + tig * 2;
            float2 bv = *(const float2*)&b[col];
            if (row0 < N_NODES) {
                __half2 o = __floats2half2_rn(fmaxf(acc[mtl][ntl][0] + bv.x, 0.f),
                                              fmaxf(acc[mtl][ntl][1] + bv.y, 0.f));
                *(__half2*)&hout[row0 * HID + col] = o;
            }
            if (row0 + 8 < N_NODES) {
                __half2 o = __floats2half2_rn(fmaxf(acc[mtl][ntl][2] + bv.x, 0.f),
                                              fmaxf(acc[mtl][ntl][3] + bv.y, 0.f));
                *(__half2*)&hout[(row0 + 8) * HID + col] = o;
            }
        }
    }
}

// ---------------- final: sigmoid(h @ Wend + bend) ----------------
__global__ void k_final(const float* __restrict__ Wend,
                        const float* __restrict__ bend,
                        float* __restrict__ out) {
    int lane = threadIdx.x & 31;
    int warp = threadIdx.x >> 5;
    int n = blockIdx.x * 8 + warp;
    if (n >= N_NODES) return;
    float s = 0.f;
#pragma unroll
    for (int c = lane * 8; c < HID; c += 256) {
        uint4 uh = *(const uint4*)&g_h16a[n * HID + c];
        const __half2* h2 = (const __half2*)&uh;
        float4 w0 = *(const float4*)&Wend[c];
        float4 w1 = *(const float4*)&Wend[c + 4];
        float2 f0 = __half22float2(h2[0]);
        float2 f1 = __half22float2(h2[1]);
        float2 f2 = __half22float2(h2[2]);
        float2 f3 = __half22float2(h2[3]);
        s += f0.x * w0.x + f0.y * w0.y + f1.x * w0.z + f1.y * w0.w;
        s += f2.x * w1.x + f2.y * w1.y + f3.x * w1.z + f3.y * w1.w;
    }
#pragma unroll
    for (int o = 16; o; o >>= 1) s += __shfl_xor_sync(0xffffffffu, s, o);
    if (lane == 0) out[n] = 1.f / (1.f + __expf(-(s + bend[0])));
}

// ---------------- host ----------------
extern "C" void kernel_launch(void* const* d_in, const int* in_sizes, int n_in,
                              void* d_out, int out_size) {
    const float* x    = (const float*)d_in[0];
    const void*  ei   = d_in[1];
    const float* ea   = (const float*)d_in[2];
    const float* We1  = (const float*)d_in[3];
    const float* be1  = (const float*)d_in[4];
    const float* W1   = (const float*)d_in[5];
    const float* b1   = (const float*)d_in[6];
    const float* We2  = (const float*)d_in[7];
    const float* be2  = (const float*)d_in[8];
    const float* W2   = (const float*)d_in[9];
    const float* b2   = (const float*)d_in[10];
    const float* Wend = (const float*)d_in[11];
    const float* bend = (const float*)d_in[12];
    float* out = (float*)d_out;

    k_prep<<<256, 256>>>(ei, W2);                                     // 0
    k_hist<<<(N_EDGES + 255) / 256, 256>>>(ei);                       // 1
    k_scan1<<<SCAN_B, 256>>>();                                       // 2
    k_fillscat<<<(N_EDGES + 255) / 256, 256>>>(ei, ea, x, We1, be1);  // 3
    k_layer1nn<<<N_NODES, 256>>>(x, W1, b1);                          // 4

    // layer 2
    k_aggr<<<(N_NODES * 32 + 255) / 256, 256>>>(0, We2, be2);
    k_gemm_tc<<<dim3(2, (N_NODES + 127) / 128), 256>>>(2, b2);

    // layer 3
    k_aggr<<<(N_NODES * 32 + 255) / 256, 256>>>(1, We2, be2);
    k_gemm_tc<<<dim3(2, (N_NODES + 127) / 128), 256>>>(3, b2);

    k_final<<<(N_NODES + 7) / 8, 256>>>(Wend, bend, out);
}